// round 10
// baseline (speedup 1.0000x reference)
#include <cuda_runtime.h>
#include <cuda_bf16.h>
#include <math.h>
#include <stdint.h>

namespace {
constexpr int H  = 1024;
constexpr int V  = 50000;
constexpr int B  = 64;
constexpr int L  = 256;
constexpr int H3 = 3 * H;
constexpr int K2 = 2 * H;

// ---- gates GEMM (mma.sync, KT=32, static smem) ----
constexpr int JT = 128;
constexpr int KT = 32;
constexpr int AST = 40;
constexpr int CST = 132;
constexpr int W_BUF_BYTES = 128 * 32 * 4;
constexpr int A_OFF       = 2 * W_BUF_BYTES;
constexpr int A_HALF      = 64 * AST * 2;
constexpr int SMEM_BYTES  = A_OFF + 2 * A_HALF;   // 43008

// ---- logits GEMM (mma.sync, KT=64, dynamic smem, K=1024 per launch) ----
constexpr int LTJ    = 128;                 // j rows per block
constexpr int LTK    = 64;                  // k per stage
constexpr int LNS_H  = H / LTK;             // 16 stages per half
constexpr int LW_BUF = LTJ * LTK * 4;       // 32768 per W stage buffer
constexpr int L_AST  = 72;                  // A smem row stride (bf16)
constexpr int LA_OFF = 2 * LW_BUF;          // 65536
constexpr int LA_HALF = 64 * L_AST * 2;     // 9216
constexpr int LA_BUF  = 2 * LA_HALF;        // 18432 (hi+lo) per buffer
constexpr int L_SMEM  = LA_OFF + 2 * LA_BUF; // 102400
}

// ---------------- scratch (device globals) ----------------------------------
__device__ __align__(16) __nv_bfloat16 g_x_hi[B * H],   g_x_lo[B * H];
__device__ __align__(16) __nv_bfloat16 g_h_hi[B * H],   g_h_lo[B * H];
__device__ __align__(16) __nv_bfloat16 g_cat_hi[B * K2], g_cat_lo[B * K2];
__device__ __align__(16) float g_gi[B * H3];
__device__ __align__(16) float g_gh[B * H3];

// ---------------- helpers ----------------------------------------------------
__device__ __forceinline__ float warp_sum(float v) {
#pragma unroll
    for (int o = 16; o > 0; o >>= 1) v += __shfl_xor_sync(0xFFFFFFFFu, v, o);
    return v;
}
__device__ __forceinline__ float warp_max(float v) {
#pragma unroll
    for (int o = 16; o > 0; o >>= 1) v = fmaxf(v, __shfl_xor_sync(0xFFFFFFFFu, v, o));
    return v;
}
__device__ __forceinline__ void split_bf16(float v, __nv_bfloat16& h, __nv_bfloat16& l) {
    h = __float2bfloat16(v);
    l = __float2bfloat16(v - __bfloat162float(h));
}
__device__ __forceinline__ uint32_t lds2(const __nv_bfloat16* p) {
    return *reinterpret_cast<const uint32_t*>(p);
}
// split a float2 into packed bf16x2 hi and lo (lo = exact residual, RN)
__device__ __forceinline__ void split2(float2 f, uint32_t& hp, uint32_t& lp) {
    asm("cvt.rn.bf16x2.f32 %0, %1, %2;" : "=r"(hp) : "f"(f.y), "f"(f.x));
    float hx = __uint_as_float(hp << 16);
    float hy = __uint_as_float(hp & 0xFFFF0000u);
    float lx = f.x - hx;
    float ly = f.y - hy;
    asm("cvt.rn.bf16x2.f32 %0, %1, %2;" : "=r"(lp) : "f"(ly), "f"(lx));
}
__device__ __forceinline__ void mma16816(float* d, const uint32_t* a, const uint32_t* b) {
    asm volatile(
        "mma.sync.aligned.m16n8k16.row.col.f32.bf16.bf16.f32 "
        "{%0,%1,%2,%3}, {%4,%5,%6,%7}, {%8,%9}, {%0,%1,%2,%3};\n"
        : "+f"(d[0]), "+f"(d[1]), "+f"(d[2]), "+f"(d[3])
        : "r"(a[0]), "r"(a[1]), "r"(a[2]), "r"(a[3]), "r"(b[0]), "r"(b[1]));
}
__device__ __forceinline__ void cp16(uint32_t dst, const void* src) {
    asm volatile("cp.async.cg.shared.global [%0], [%1], 16;\n" :: "r"(dst), "l"(src));
}
__device__ __forceinline__ void cp_commit() {
    asm volatile("cp.async.commit_group;\n" ::: "memory");
}

// ---------------- K1: prep = embedding gather+relu+split AND hid split -------
__global__ void k_prep(const int* __restrict__ ids, const float* __restrict__ emb,
                       const float* __restrict__ hid) {
    if (blockIdx.x < B) {
        int b = blockIdx.x;
        const float* src = emb + (size_t)ids[b] * H;
        for (int h = threadIdx.x; h < H; h += 256) {
            float v = fmaxf(src[h], 0.0f);
            split_bf16(v, g_x_hi[b * H + h], g_x_lo[b * H + h]);
        }
    } else {
        int base = (blockIdx.x - B) * 4096;
#pragma unroll
        for (int k = 0; k < 16; k++) {
            int i = base + threadIdx.x + k * 256;
            split_bf16(hid[i], g_h_hi[i], g_h_lo[i]);
        }
    }
}

// ---------------- pipelined mma.sync body (gates GEMM, KT=32) ----------------
__device__ __forceinline__ void mma_gemm_body(
    unsigned char* smem,
    const __nv_bfloat16* __restrict__ Ahi, const __nv_bfloat16* __restrict__ Alo,
    const float* __restrict__ W, const float* __restrict__ bias,
    float* __restrict__ out, int K, int J, int ldo, int j0)
{
    __nv_bfloat16* sAh = reinterpret_cast<__nv_bfloat16*>(smem + A_OFF);
    __nv_bfloat16* sAl = reinterpret_cast<__nv_bfloat16*>(smem + A_OFF + A_HALF);
    const uint32_t smem_u32 = (uint32_t)__cvta_generic_to_shared(smem);

    const int tid  = threadIdx.x;
    const int lane = tid & 31;
    const int wid  = tid >> 5;
    const int grp  = lane >> 2;
    const int qd   = lane & 3;
    const int jw   = (wid >> 1) * 32;
    const int bw   = (wid & 1) * 32;
    const int nk   = K / KT;

    const int wrow = tid >> 3;
    const int wkq  = (tid & 7) * 4;
    const int arow = tid >> 2;
    const int aseg = (tid & 3) * 8;

    float acc[2][4][4];
#pragma unroll
    for (int jt = 0; jt < 2; jt++)
#pragma unroll
        for (int bt = 0; bt < 4; bt++)
#pragma unroll
            for (int q = 0; q < 4; q++) acc[jt][bt][q] = 0.0f;

    {
        uint4 h0 = *(const uint4*)&Ahi[(size_t)arow * K + aseg];
        uint4 l0 = *(const uint4*)&Alo[(size_t)arow * K + aseg];
        *(uint4*)&sAh[arow * AST + aseg] = h0;
        *(uint4*)&sAl[arow * AST + aseg] = l0;
    }
    uint4 ra_h = *(const uint4*)&Ahi[(size_t)arow * K + KT + aseg];
    uint4 ra_l = *(const uint4*)&Alo[(size_t)arow * K + KT + aseg];

#pragma unroll
    for (int s = 0; s < 2; s++) {
        uint32_t wb = smem_u32 + s * W_BUF_BYTES;
#pragma unroll
        for (int i = 0; i < 4; i++) {
            int r = wrow + i * 32;
            int j = j0 + r; if (j > J - 1) j = J - 1;
            int c = wkq ^ ((r & 3) * 8);
            cp16(wb + (uint32_t)(r * 32 + c) * 4, &W[(size_t)j * K + s * KT + wkq]);
        }
        cp_commit();
    }

    const int swz = (grp & 3) * 8;

    for (int s = 0; s < nk; s++) {
        if (s + 1 < nk) asm volatile("cp.async.wait_group 1;" ::: "memory");
        else            asm volatile("cp.async.wait_group 0;" ::: "memory");
        __syncthreads();

        uint4 rb_h, rb_l;
        if (s + 2 < nk) {
            rb_h = *(const uint4*)&Ahi[(size_t)arow * K + (s + 2) * KT + aseg];
            rb_l = *(const uint4*)&Alo[(size_t)arow * K + (s + 2) * KT + aseg];
        }

        const float* sWb = reinterpret_cast<const float*>(smem + (s & 1) * W_BUF_BYTES);
#pragma unroll
        for (int ks = 0; ks < KT; ks += 16) {
            const int kc = ks + qd * 2;
            const int c0 = kc ^ swz;
            const int c1 = (kc + 8) ^ swz;
            uint32_t wh[2][4], wl[2][4];
#pragma unroll
            for (int jt = 0; jt < 2; jt++) {
                int r0 = (jw + jt * 16 + grp) * 32;
                int r1 = r0 + 8 * 32;
                float2 f0 = *(const float2*)&sWb[r0 + c0];
                float2 f1 = *(const float2*)&sWb[r1 + c0];
                float2 f2 = *(const float2*)&sWb[r0 + c1];
                float2 f3 = *(const float2*)&sWb[r1 + c1];
                split2(f0, wh[jt][0], wl[jt][0]);
                split2(f1, wh[jt][1], wl[jt][1]);
                split2(f2, wh[jt][2], wl[jt][2]);
                split2(f3, wh[jt][3], wl[jt][3]);
            }
            uint32_t ah[4][2], al[4][2];
#pragma unroll
            for (int bt = 0; bt < 4; bt++) {
                int br = bw + bt * 8 + grp;
                ah[bt][0] = lds2(&sAh[br * AST + kc]);
                ah[bt][1] = lds2(&sAh[br * AST + kc + 8]);
                al[bt][0] = lds2(&sAl[br * AST + kc]);
                al[bt][1] = lds2(&sAl[br * AST + kc + 8]);
            }
#pragma unroll
            for (int jt = 0; jt < 2; jt++)
#pragma unroll
                for (int bt = 0; bt < 4; bt++) {
                    mma16816(acc[jt][bt], wh[jt], ah[bt]);
                    mma16816(acc[jt][bt], wh[jt], al[bt]);
                    mma16816(acc[jt][bt], wl[jt], ah[bt]);
                }
        }
        __syncthreads();

        if (s + 1 < nk) {
            *(uint4*)&sAh[arow * AST + aseg] = ra_h;
            *(uint4*)&sAl[arow * AST + aseg] = ra_l;
            ra_h = rb_h; ra_l = rb_l;
        }
        if (s + 2 < nk) {
            uint32_t wb = smem_u32 + ((s + 2) & 1) * W_BUF_BYTES;
#pragma unroll
            for (int i = 0; i < 4; i++) {
                int r = wrow + i * 32;
                int j = j0 + r; if (j > J - 1) j = J - 1;
                int c = wkq ^ ((r & 3) * 8);
                cp16(wb + (uint32_t)(r * 32 + c) * 4, &W[(size_t)j * K + (s + 2) * KT + wkq]);
            }
            cp_commit();
        }
    }

    float* Ct = reinterpret_cast<float*>(smem);
#pragma unroll
    for (int jt = 0; jt < 2; jt++)
#pragma unroll
        for (int bt = 0; bt < 4; bt++) {
            int jl = jw + jt * 16 + grp;
            int bl = bw + bt * 8 + qd * 2;
            Ct[bl * CST + jl]           = acc[jt][bt][0];
            Ct[(bl + 1) * CST + jl]     = acc[jt][bt][1];
            Ct[bl * CST + jl + 8]       = acc[jt][bt][2];
            Ct[(bl + 1) * CST + jl + 8] = acc[jt][bt][3];
        }
    __syncthreads();
#pragma unroll
    for (int p = 0; p < 8; p++) {
        int brow = (tid >> 5) + p * 8;
        int col  = lane * 4;
        float4 c = *(const float4*)&Ct[brow * CST + col];
        int j = j0 + col;
        if (j + 3 < J) {
            float4 o;
            o.x = c.x + bias[j];     o.y = c.y + bias[j + 1];
            o.z = c.z + bias[j + 2]; o.w = c.w + bias[j + 3];
            *(float4*)&out[(size_t)brow * ldo + j] = o;
        } else {
            float cv[4] = {c.x, c.y, c.z, c.w};
#pragma unroll
            for (int q = 0; q < 4; q++)
                if (j + q < J) out[(size_t)brow * ldo + j + q] = cv[q] + bias[j + q];
        }
    }
}

// ---------------- K2: GRU gate GEMMs ----------------------------------------
__global__ __launch_bounds__(256, 2) void k_gates_gemm(
    const float* __restrict__ w_ih, const float* __restrict__ w_hh,
    const float* __restrict__ b_ih, const float* __restrict__ b_hh)
{
    __shared__ __align__(16) unsigned char smem[SMEM_BYTES];
    constexpr int NB = H3 / JT;
    bool second = blockIdx.x >= NB;
    int j0 = (second ? blockIdx.x - NB : blockIdx.x) * JT;
    const __nv_bfloat16* Ahi = second ? g_h_hi : g_x_hi;
    const __nv_bfloat16* Alo = second ? g_h_lo : g_x_lo;
    const float* W    = second ? w_hh : w_ih;
    const float* bias = second ? b_hh : b_ih;
    float* out        = second ? g_gh : g_gi;
    mma_gemm_body(smem, Ahi, Alo, W, bias, out, H, H3, H3, j0);
}

// ---------------- K3: fused GRU + cosine sim + softmax + context -------------
__global__ __launch_bounds__(512) void k_gru_attn(
    const float* __restrict__ hid, const float* __restrict__ enc,
    float* __restrict__ hout, float* __restrict__ aout)
{
    __shared__ float sh_h[H];
    __shared__ float sim_s[L];
    __shared__ float attn_s[L];
    __shared__ float red[16];
    __shared__ float s_norm, s_bcast;

    int b = blockIdx.x;
    int tid = threadIdx.x, lane = tid & 31, wid = tid >> 5;

    // ---- GRU ----
    float ss = 0.0f;
#pragma unroll
    for (int k = 0; k < 2; k++) {
        int j = tid + k * 512;
        float ir = g_gi[b * H3 + j],          hr = g_gh[b * H3 + j];
        float iz = g_gi[b * H3 + H + j],      hz = g_gh[b * H3 + H + j];
        float in_ = g_gi[b * H3 + 2 * H + j], hn = g_gh[b * H3 + 2 * H + j];
        float r = 1.0f / (1.0f + expf(-(ir + hr)));
        float z = 1.0f / (1.0f + expf(-(iz + hz)));
        float n = tanhf(in_ + r * hn);
        float hv = hid[b * H + j];
        float hnew = (1.0f - z) * n + z * hv;
        sh_h[j] = hnew;
        hout[b * H + j] = hnew;
        split_bf16(hnew, g_cat_hi[b * K2 + j], g_cat_lo[b * K2 + j]);
        ss += hnew * hnew;
    }
    float w = warp_sum(ss);
    if (lane == 0) red[wid] = w;
    __syncthreads();
    if (tid == 0) {
        float t = 0.0f;
#pragma unroll
        for (int i = 0; i < 16; i++) t += red[i];
        s_norm = fmaxf(sqrtf(t), 1e-7f);
    }
    __syncthreads();
    float nrm = s_norm;

    // ---- cosine similarities: warp wid handles l = wid*16 .. +15 ----
    const float4* sh4 = reinterpret_cast<const float4*>(sh_h);
    for (int r = 0; r < 16; r++) {
        int l = wid * 16 + r;
        const float4* e4 = (const float4*)(enc + (size_t)l * (B * H) + (size_t)b * H);
        float dot = 0.0f, sq = 0.0f;
#pragma unroll
        for (int it = 0; it < 8; it++) {
            float4 ev = e4[lane + it * 32];
            float4 hv = sh4[lane + it * 32];
            dot += ev.x * hv.x + ev.y * hv.y + ev.z * hv.z + ev.w * hv.w;
            sq  += ev.x * ev.x + ev.y * ev.y + ev.z * ev.z + ev.w * ev.w;
        }
        dot = warp_sum(dot);
        sq  = warp_sum(sq);
        if (lane == 0)
            sim_s[l] = dot / (nrm * fmaxf(sqrtf(sq), 1e-7f));
    }
    __syncthreads();

    // ---- softmax over l (256 values, 512 threads) ----
    float v = (tid < L) ? sim_s[tid] : -3.4e38f;
    float m = warp_max(v);
    if (lane == 0) red[wid] = m;
    __syncthreads();
    if (tid == 0) {
        float t = red[0];
#pragma unroll
        for (int i = 1; i < 16; i++) t = fmaxf(t, red[i]);
        s_bcast = t;
    }
    __syncthreads();
    float e = (tid < L) ? expf(v - s_bcast) : 0.0f;
    float s = warp_sum(e);
    if (lane == 0) red[wid] = s;
    __syncthreads();
    if (tid == 0) {
        float t = 0.0f;
#pragma unroll
        for (int i = 0; i < 16; i++) t += red[i];
        s_bcast = t;
    }
    __syncthreads();
    if (tid < L) {
        float a = e / s_bcast;
        attn_s[tid] = a;
        aout[b * L + tid] = a;
    }
    __syncthreads();

    // ---- context: ctx[b, tid*2 .. +1] (enc second pass, mostly L2) ----
    float2 acc = make_float2(0.0f, 0.0f);
    const float* ebase = enc + (size_t)b * H + tid * 2;
#pragma unroll 4
    for (int l = 0; l < L; l++) {
        float2 ev = *(const float2*)(ebase + (size_t)l * (B * H));
        float a = attn_s[l];
        acc.x += a * ev.x;
        acc.y += a * ev.y;
    }
    int h0 = H + tid * 2;
    split_bf16(acc.x, g_cat_hi[(size_t)b * K2 + h0],     g_cat_lo[(size_t)b * K2 + h0]);
    split_bf16(acc.y, g_cat_hi[(size_t)b * K2 + h0 + 1], g_cat_lo[(size_t)b * K2 + h0 + 1]);
}

// ---------------- K4/K5: logits GEMM half (K=1024 per launch) ----------------
// koff = 0: out = W[:, :H]·h_new + bias   (write)
// koff = H: out += W[:, H:]·ctx           (accumulate)
__global__ __launch_bounds__(256, 2) void k_logits_half(
    const float* __restrict__ W, const float* __restrict__ bias,
    float* __restrict__ out, int koff, int acc_flag)
{
    extern __shared__ __align__(16) unsigned char dsm[];
    const uint32_t smem_u32 = (uint32_t)__cvta_generic_to_shared(dsm);
    const int tid  = threadIdx.x;
    const int lane = tid & 31;
    const int wid  = tid >> 5;
    const int grp  = lane >> 2;
    const int qd   = lane & 3;
    const int jw   = (wid >> 1) * 32;
    const int bw   = (wid & 1) * 32;
    const int j0   = blockIdx.x * LTJ;
    const int swz  = (grp & 3) * 8;

    const int wrow0 = tid >> 4;
    const int wcol  = (tid & 15) * 4;
    const int arow = tid >> 2;
    const int acol = (tid & 3) * 16;

    float acc[2][4][4];
#pragma unroll
    for (int jt = 0; jt < 2; jt++)
#pragma unroll
        for (int bt = 0; bt < 4; bt++)
#pragma unroll
            for (int q = 0; q < 4; q++) acc[jt][bt][q] = 0.0f;

    const __nv_bfloat16* Ah = g_cat_hi + (size_t)arow * K2 + koff + acol;
    const __nv_bfloat16* Al = g_cat_lo + (size_t)arow * K2 + koff + acol;

    {
        __nv_bfloat16* sh = (__nv_bfloat16*)(dsm + LA_OFF);
        __nv_bfloat16* sl = (__nv_bfloat16*)(dsm + LA_OFF + LA_HALF);
        *(uint4*)&sh[arow * L_AST + acol]     = *(const uint4*)Ah;
        *(uint4*)&sh[arow * L_AST + acol + 8] = *(const uint4*)(Ah + 8);
        *(uint4*)&sl[arow * L_AST + acol]     = *(const uint4*)Al;
        *(uint4*)&sl[arow * L_AST + acol + 8] = *(const uint4*)(Al + 8);
    }
    uint4 rh0 = *(const uint4*)(Ah + LTK),     rh1 = *(const uint4*)(Ah + LTK + 8);
    uint4 rl0 = *(const uint4*)(Al + LTK),     rl1 = *(const uint4*)(Al + LTK + 8);

#pragma unroll
    for (int s = 0; s < 2; s++) {
        uint32_t wb = smem_u32 + s * LW_BUF;
#pragma unroll
        for (int i = 0; i < 8; i++) {
            int r = wrow0 + i * 16;
            int j = j0 + r; if (j > V - 1) j = V - 1;
            int c = wcol ^ ((r & 3) * 8);
            cp16(wb + (uint32_t)(r * LTK + c) * 4, &W[(size_t)j * K2 + koff + s * LTK + wcol]);
        }
        cp_commit();
    }

    for (int s = 0; s < LNS_H; s++) {
        if (s + 1 < LNS_H) asm volatile("cp.async.wait_group 1;" ::: "memory");
        else               asm volatile("cp.async.wait_group 0;" ::: "memory");
        __syncthreads();

        uint4 nh0, nh1, nl0, nl1;
        if (s + 2 < LNS_H) {
            nh0 = *(const uint4*)(Ah + (s + 2) * LTK);
            nh1 = *(const uint4*)(Ah + (s + 2) * LTK + 8);
            nl0 = *(const uint4*)(Al + (s + 2) * LTK);
            nl1 = *(const uint4*)(Al + (s + 2) * LTK + 8);
        }

        const float* sWb = reinterpret_cast<const float*>(dsm + (s & 1) * LW_BUF);
        const __nv_bfloat16* sAh_ = (const __nv_bfloat16*)(dsm + LA_OFF + (s & 1) * LA_BUF);
        const __nv_bfloat16* sAl_ = (const __nv_bfloat16*)(dsm + LA_OFF + (s & 1) * LA_BUF + LA_HALF);

#pragma unroll
        for (int ks = 0; ks < LTK; ks += 16) {
            const int kc = ks + qd * 2;
            const int c0 = kc ^ swz;
            const int c1 = (kc + 8) ^ swz;
            uint32_t wh[2][4], wl[2][4];
#pragma unroll
            for (int jt = 0; jt < 2; jt++) {
                int r0 = (jw + jt * 16 + grp) * LTK;
                int r1 = r0 + 8 * LTK;
                float2 f0 = *(const float2*)&sWb[r0 + c0];
                float2 f1 = *(const float2*)&sWb[r1 + c0];
                float2 f2 = *(const float2*)&sWb[r0 + c1];
                float2 f3 = *(const float2*)&sWb[r1 + c1];
                split2(f0, wh[jt][0], wl[jt][0]);
                split2(f1, wh[jt][1], wl[jt][1]);
                split2(f2, wh[jt][2], wl[jt][2]);
                split2(f3, wh[jt][3], wl[jt][3]);
            }
            uint32_t ah[4][2], al[4][2];
#pragma unroll
            for (int bt = 0; bt < 4; bt++) {
                int br = bw + bt * 8 + grp;
                ah[bt][0] = lds2(&sAh_[br * L_AST + kc]);
                ah[bt][1] = lds2(&sAh_[br * L_AST + kc + 8]);
                al[bt][0] = lds2(&sAl_[br * L_AST + kc]);
                al[bt][1] = lds2(&sAl_[br * L_AST + kc + 8]);
            }
#pragma unroll
            for (int jt = 0; jt < 2; jt++)
#pragma unroll
                for (int bt = 0; bt < 4; bt++) {
                    mma16816(acc[jt][bt], wh[jt], ah[bt]);  // hi*hi
                    mma16816(acc[jt][bt], wh[jt], al[bt]);  // hi*lo
                    mma16816(acc[jt][bt], wl[jt], ah[bt]);  // lo*hi
                }
        }
        __syncthreads();

        if (s + 1 < LNS_H) {
            __nv_bfloat16* sh = (__nv_bfloat16*)(dsm + LA_OFF + ((s + 1) & 1) * LA_BUF);
            __nv_bfloat16* sl = (__nv_bfloat16*)(dsm + LA_OFF + ((s + 1) & 1) * LA_BUF + LA_HALF);
            *(uint4*)&sh[arow * L_AST + acol]     = rh0;
            *(uint4*)&sh[arow * L_AST + acol + 8] = rh1;
            *(uint4*)&sl[arow * L_AST + acol]     = rl0;
            *(uint4*)&sl[arow * L_AST + acol + 8] = rl1;
            rh0 = nh0; rh1 = nh1; rl0 = nl0; rl1 = nl1;
        }
        if (s + 2 < LNS_H) {
            uint32_t wb = smem_u32 + ((s + 2) & 1) * LW_BUF;
#pragma unroll
            for (int i = 0; i < 8; i++) {
                int r = wrow0 + i * 16;
                int j = j0 + r; if (j > V - 1) j = V - 1;
                int c = wcol ^ ((r & 3) * 8);
                cp16(wb + (uint32_t)(r * LTK + c) * 4,
                     &W[(size_t)j * K2 + koff + (s + 2) * LTK + wcol]);
            }
            cp_commit();
        }
    }

    // ---- epilogue ----
    float* Ct = reinterpret_cast<float*>(dsm);
#pragma unroll
    for (int jt = 0; jt < 2; jt++)
#pragma unroll
        for (int bt = 0; bt < 4; bt++) {
            int jl = jw + jt * 16 + grp;
            int bl = bw + bt * 8 + qd * 2;
            Ct[bl * CST + jl]           = acc[jt][bt][0];
            Ct[(bl + 1) * CST + jl]     = acc[jt][bt][1];
            Ct[bl * CST + jl + 8]       = acc[jt][bt][2];
            Ct[(bl + 1) * CST + jl + 8] = acc[jt][bt][3];
        }
    __syncthreads();
#pragma unroll
    for (int p = 0; p < 8; p++) {
        int brow = (tid >> 5) + p * 8;
        int col  = lane * 4;
        float4 c = *(const float4*)&Ct[brow * CST + col];
        int j = j0 + col;
        if (j + 3 < V) {
            float4 o;
            if (acc_flag) {
                float4 prev = *(const float4*)&out[(size_t)brow * V + j];
                o.x = prev.x + c.x; o.y = prev.y + c.y;
                o.z = prev.z + c.z; o.w = prev.w + c.w;
            } else {
                o.x = c.x + bias[j];     o.y = c.y + bias[j + 1];
                o.z = c.z + bias[j + 2]; o.w = c.w + bias[j + 3];
            }
            *(float4*)&out[(size_t)brow * V + j] = o;
        } else {
            float cv[4] = {c.x, c.y, c.z, c.w};
#pragma unroll
            for (int q = 0; q < 4; q++)
                if (j + q < V) {
                    if (acc_flag) out[(size_t)brow * V + j + q] += cv[q];
                    else          out[(size_t)brow * V + j + q] = cv[q] + bias[j + q];
                }
        }
    }
}

// ---------------- K6: log_softmax over V, in place (float4) ------------------
__global__ void k_lse(float* __restrict__ logp) {
    int b = blockIdx.x;
    float* row = logp + (size_t)b * V;
    float4* row4 = reinterpret_cast<float4*>(row);
    constexpr int V4 = V / 4;
    __shared__ float sm[32];
    __shared__ float bcast;
    int tid = threadIdx.x, wid = tid >> 5, lane = tid & 31;

    float m = -3.4e38f;
    for (int v = tid; v < V4; v += 1024) {
        float4 c = row4[v];
        m = fmaxf(m, fmaxf(fmaxf(c.x, c.y), fmaxf(c.z, c.w)));
    }
    m = warp_max(m);
    if (lane == 0) sm[wid] = m;
    __syncthreads();
    if (tid == 0) {
        float t = sm[0];
#pragma unroll
        for (int i = 1; i < 32; i++) t = fmaxf(t, sm[i]);
        bcast = t;
    }
    __syncthreads();
    float bm = bcast;

    float s = 0.0f;
    for (int v = tid; v < V4; v += 1024) {
        float4 c = row4[v];
        s += expf(c.x - bm) + expf(c.y - bm) + expf(c.z - bm) + expf(c.w - bm);
    }
    s = warp_sum(s);
    if (lane == 0) sm[wid] = s;
    __syncthreads();
    if (tid == 0) {
        float t = 0.0f;
#pragma unroll
        for (int i = 0; i < 32; i++) t += sm[i];
        bcast = bm + logf(t);
    }
    __syncthreads();
    float ls = bcast;
    for (int v = tid; v < V4; v += 1024) {
        float4 c = row4[v];
        c.x -= ls; c.y -= ls; c.z -= ls; c.w -= ls;
        row4[v] = c;
    }
}

// ---------------- launch -----------------------------------------------------
extern "C" void kernel_launch(void* const* d_in, const int* in_sizes, int n_in,
                              void* d_out, int out_size) {
    const int*   ids   = (const int*)  d_in[0];
    const float* hid   = (const float*)d_in[1];
    const float* enc   = (const float*)d_in[2];
    const float* emb   = (const float*)d_in[3];
    const float* w_ih  = (const float*)d_in[4];
    const float* w_hh  = (const float*)d_in[5];
    const float* b_ih  = (const float*)d_in[6];
    const float* b_hh  = (const float*)d_in[7];
    const float* w_out = (const float*)d_in[8];
    const float* b_out = (const float*)d_in[9];

    float* out  = (float*)d_out;
    float* logp = out;                       // [B][V]
    float* hout = out + (size_t)B * V;       // [1][B][H]
    float* aout = hout + (size_t)B * H;      // [B][L]

    cudaFuncSetAttribute(k_logits_half,
                         cudaFuncAttributeMaxDynamicSharedMemorySize, L_SMEM);

    k_prep<<<B + 16, 256>>>(ids, emb, hid);                              // 1
    k_gates_gemm<<<2 * (H3 / JT), 256>>>(w_ih, w_hh, b_ih, b_hh);        // 2
    k_gru_attn<<<B, 512>>>(hid, enc, hout, aout);                        // 3
    k_logits_half<<<(V + LTJ - 1) / LTJ, 256, L_SMEM>>>(                 // 4 (profiled)
        w_out, b_out, logp, 0, 0);
    k_logits_half<<<(V + LTJ - 1) / LTJ, 256, L_SMEM>>>(                 // 5
        w_out, b_out, logp, H, 1);
    k_lse<<<B, 1024>>>(logp);                                            // 6
}

// round 11
// speedup vs baseline: 1.5537x; 1.5537x over previous
#include <cuda_runtime.h>
#include <cuda_bf16.h>
#include <cuda_fp16.h>
#include <math.h>
#include <stdint.h>

namespace {
constexpr int H  = 1024;
constexpr int V  = 50000;
constexpr int B  = 64;
constexpr int L  = 256;
constexpr int H3 = 3 * H;
constexpr int K2 = 2 * H;

// ---- gates GEMM (mma.sync bf16 3-pass, KT=32, static smem) ----
constexpr int JT = 128;
constexpr int KT = 32;
constexpr int AST = 40;
constexpr int CST = 132;
constexpr int W_BUF_BYTES = 128 * 32 * 4;
constexpr int A_OFF       = 2 * W_BUF_BYTES;
constexpr int A_HALF      = 64 * AST * 2;
constexpr int SMEM_BYTES  = A_OFF + 2 * A_HALF;   // 43008

// ---- logits GEMM (mma.sync fp16 1-pass, KT=64, dynamic smem) ----
constexpr int LTJ    = 128;                 // j rows per block
constexpr int LTK    = 64;                  // k per stage
constexpr int LNS    = K2 / LTK;            // 32 stages
constexpr int LW_BUF = LTJ * LTK * 4;       // 32768 per W stage buffer
constexpr int L_AST  = 72;                  // A smem row stride (fp16 elements)
constexpr int LA_OFF = 2 * LW_BUF;          // 65536
constexpr int LA_BUF = 64 * L_AST * 2;      // 9216 bytes per A buffer (single fp16)
constexpr int L_SMEM = LA_OFF + 2 * LA_BUF; // 83968
}

// ---------------- scratch (device globals) ----------------------------------
__device__ __align__(16) __nv_bfloat16 g_x_hi[B * H],   g_x_lo[B * H];
__device__ __align__(16) __nv_bfloat16 g_h_hi[B * H],   g_h_lo[B * H];
__device__ __align__(16) __half g_cat_f16[B * K2];      // [h_new | ctx] fp16
__device__ __align__(16) float g_gi[B * H3];
__device__ __align__(16) float g_gh[B * H3];
__device__ float g_norm[B];
__device__ float g_sim[B * L];
__device__ float g_attn[B * L];

// ---------------- helpers ----------------------------------------------------
__device__ __forceinline__ float warp_sum(float v) {
#pragma unroll
    for (int o = 16; o > 0; o >>= 1) v += __shfl_xor_sync(0xFFFFFFFFu, v, o);
    return v;
}
__device__ __forceinline__ float warp_max(float v) {
#pragma unroll
    for (int o = 16; o > 0; o >>= 1) v = fmaxf(v, __shfl_xor_sync(0xFFFFFFFFu, v, o));
    return v;
}
__device__ __forceinline__ void split_bf16(float v, __nv_bfloat16& h, __nv_bfloat16& l) {
    h = __float2bfloat16(v);
    l = __float2bfloat16(v - __bfloat162float(h));
}
__device__ __forceinline__ uint32_t lds2h(const __half* p) {
    return *reinterpret_cast<const uint32_t*>(p);
}
__device__ __forceinline__ uint32_t lds2b(const __nv_bfloat16* p) {
    return *reinterpret_cast<const uint32_t*>(p);
}
// split a float2 into packed bf16x2 hi and lo (lo = exact residual, RN)
__device__ __forceinline__ void split2(float2 f, uint32_t& hp, uint32_t& lp) {
    asm("cvt.rn.bf16x2.f32 %0, %1, %2;" : "=r"(hp) : "f"(f.y), "f"(f.x));
    float hx = __uint_as_float(hp << 16);
    float hy = __uint_as_float(hp & 0xFFFF0000u);
    float lx = f.x - hx;
    float ly = f.y - hy;
    asm("cvt.rn.bf16x2.f32 %0, %1, %2;" : "=r"(lp) : "f"(ly), "f"(lx));
}
// float2 -> packed fp16x2 (RN)
__device__ __forceinline__ uint32_t f2h2(float2 f) {
    uint32_t h;
    asm("cvt.rn.f16x2.f32 %0, %1, %2;" : "=r"(h) : "f"(f.y), "f"(f.x));
    return h;
}
__device__ __forceinline__ void mma_bf16(float* d, const uint32_t* a, const uint32_t* b) {
    asm volatile(
        "mma.sync.aligned.m16n8k16.row.col.f32.bf16.bf16.f32 "
        "{%0,%1,%2,%3}, {%4,%5,%6,%7}, {%8,%9}, {%0,%1,%2,%3};\n"
        : "+f"(d[0]), "+f"(d[1]), "+f"(d[2]), "+f"(d[3])
        : "r"(a[0]), "r"(a[1]), "r"(a[2]), "r"(a[3]), "r"(b[0]), "r"(b[1]));
}
__device__ __forceinline__ void mma_f16(float* d, const uint32_t* a, const uint32_t* b) {
    asm volatile(
        "mma.sync.aligned.m16n8k16.row.col.f32.f16.f16.f32 "
        "{%0,%1,%2,%3}, {%4,%5,%6,%7}, {%8,%9}, {%0,%1,%2,%3};\n"
        : "+f"(d[0]), "+f"(d[1]), "+f"(d[2]), "+f"(d[3])
        : "r"(a[0]), "r"(a[1]), "r"(a[2]), "r"(a[3]), "r"(b[0]), "r"(b[1]));
}
__device__ __forceinline__ void cp16(uint32_t dst, const void* src) {
    asm volatile("cp.async.cg.shared.global [%0], [%1], 16;\n" :: "r"(dst), "l"(src));
}
__device__ __forceinline__ void cp_commit() {
    asm volatile("cp.async.commit_group;\n" ::: "memory");
}

// ---------------- K0: embedding gather + relu + split ------------------------
__global__ void k_embed(const int* __restrict__ ids, const float* __restrict__ emb) {
    int b = blockIdx.x;
    const float* src = emb + (size_t)ids[b] * H;
    for (int h = threadIdx.x; h < H; h += blockDim.x) {
        float v = fmaxf(src[h], 0.0f);
        split_bf16(v, g_x_hi[b * H + h], g_x_lo[b * H + h]);
    }
}
__global__ void k_split_hid(const float* __restrict__ hid) {
    int i = blockIdx.x * 256 + threadIdx.x;
    if (i < B * H) split_bf16(hid[i], g_h_hi[i], g_h_lo[i]);
}

// ---------------- pipelined bf16 3-pass body (gates GEMM, KT=32) -------------
__device__ __forceinline__ void mma_gemm_body(
    unsigned char* smem,
    const __nv_bfloat16* __restrict__ Ahi, const __nv_bfloat16* __restrict__ Alo,
    const float* __restrict__ W, const float* __restrict__ bias,
    float* __restrict__ out, int K, int J, int ldo, int j0)
{
    __nv_bfloat16* sAh = reinterpret_cast<__nv_bfloat16*>(smem + A_OFF);
    __nv_bfloat16* sAl = reinterpret_cast<__nv_bfloat16*>(smem + A_OFF + A_HALF);
    const uint32_t smem_u32 = (uint32_t)__cvta_generic_to_shared(smem);

    const int tid  = threadIdx.x;
    const int lane = tid & 31;
    const int wid  = tid >> 5;
    const int grp  = lane >> 2;
    const int qd   = lane & 3;
    const int jw   = (wid >> 1) * 32;
    const int bw   = (wid & 1) * 32;
    const int nk   = K / KT;

    const int wrow = tid >> 3;
    const int wkq  = (tid & 7) * 4;
    const int arow = tid >> 2;
    const int aseg = (tid & 3) * 8;

    float acc[2][4][4];
#pragma unroll
    for (int jt = 0; jt < 2; jt++)
#pragma unroll
        for (int bt = 0; bt < 4; bt++)
#pragma unroll
            for (int q = 0; q < 4; q++) acc[jt][bt][q] = 0.0f;

    {
        uint4 h0 = *(const uint4*)&Ahi[(size_t)arow * K + aseg];
        uint4 l0 = *(const uint4*)&Alo[(size_t)arow * K + aseg];
        *(uint4*)&sAh[arow * AST + aseg] = h0;
        *(uint4*)&sAl[arow * AST + aseg] = l0;
    }
    uint4 ra_h = *(const uint4*)&Ahi[(size_t)arow * K + KT + aseg];
    uint4 ra_l = *(const uint4*)&Alo[(size_t)arow * K + KT + aseg];

#pragma unroll
    for (int s = 0; s < 2; s++) {
        uint32_t wb = smem_u32 + s * W_BUF_BYTES;
#pragma unroll
        for (int i = 0; i < 4; i++) {
            int r = wrow + i * 32;
            int j = j0 + r; if (j > J - 1) j = J - 1;
            int c = wkq ^ ((r & 3) * 8);
            cp16(wb + (uint32_t)(r * 32 + c) * 4, &W[(size_t)j * K + s * KT + wkq]);
        }
        cp_commit();
    }

    const int swz = (grp & 3) * 8;

    for (int s = 0; s < nk; s++) {
        if (s + 1 < nk) asm volatile("cp.async.wait_group 1;" ::: "memory");
        else            asm volatile("cp.async.wait_group 0;" ::: "memory");
        __syncthreads();

        uint4 rb_h, rb_l;
        if (s + 2 < nk) {
            rb_h = *(const uint4*)&Ahi[(size_t)arow * K + (s + 2) * KT + aseg];
            rb_l = *(const uint4*)&Alo[(size_t)arow * K + (s + 2) * KT + aseg];
        }

        const float* sWb = reinterpret_cast<const float*>(smem + (s & 1) * W_BUF_BYTES);
#pragma unroll
        for (int ks = 0; ks < KT; ks += 16) {
            const int kc = ks + qd * 2;
            const int c0 = kc ^ swz;
            const int c1 = (kc + 8) ^ swz;
            uint32_t wh[2][4], wl[2][4];
#pragma unroll
            for (int jt = 0; jt < 2; jt++) {
                int r0 = (jw + jt * 16 + grp) * 32;
                int r1 = r0 + 8 * 32;
                float2 f0 = *(const float2*)&sWb[r0 + c0];
                float2 f1 = *(const float2*)&sWb[r1 + c0];
                float2 f2 = *(const float2*)&sWb[r0 + c1];
                float2 f3 = *(const float2*)&sWb[r1 + c1];
                split2(f0, wh[jt][0], wl[jt][0]);
                split2(f1, wh[jt][1], wl[jt][1]);
                split2(f2, wh[jt][2], wl[jt][2]);
                split2(f3, wh[jt][3], wl[jt][3]);
            }
            uint32_t ah[4][2], al[4][2];
#pragma unroll
            for (int bt = 0; bt < 4; bt++) {
                int br = bw + bt * 8 + grp;
                ah[bt][0] = lds2b(&sAh[br * AST + kc]);
                ah[bt][1] = lds2b(&sAh[br * AST + kc + 8]);
                al[bt][0] = lds2b(&sAl[br * AST + kc]);
                al[bt][1] = lds2b(&sAl[br * AST + kc + 8]);
            }
#pragma unroll
            for (int jt = 0; jt < 2; jt++)
#pragma unroll
                for (int bt = 0; bt < 4; bt++) {
                    mma_bf16(acc[jt][bt], wh[jt], ah[bt]);
                    mma_bf16(acc[jt][bt], wh[jt], al[bt]);
                    mma_bf16(acc[jt][bt], wl[jt], ah[bt]);
                }
        }
        __syncthreads();

        if (s + 1 < nk) {
            *(uint4*)&sAh[arow * AST + aseg] = ra_h;
            *(uint4*)&sAl[arow * AST + aseg] = ra_l;
            ra_h = rb_h; ra_l = rb_l;
        }
        if (s + 2 < nk) {
            uint32_t wb = smem_u32 + ((s + 2) & 1) * W_BUF_BYTES;
#pragma unroll
            for (int i = 0; i < 4; i++) {
                int r = wrow + i * 32;
                int j = j0 + r; if (j > J - 1) j = J - 1;
                int c = wkq ^ ((r & 3) * 8);
                cp16(wb + (uint32_t)(r * 32 + c) * 4, &W[(size_t)j * K + (s + 2) * KT + wkq]);
            }
            cp_commit();
        }
    }

    float* Ct = reinterpret_cast<float*>(smem);
#pragma unroll
    for (int jt = 0; jt < 2; jt++)
#pragma unroll
        for (int bt = 0; bt < 4; bt++) {
            int jl = jw + jt * 16 + grp;
            int bl = bw + bt * 8 + qd * 2;
            Ct[bl * CST + jl]           = acc[jt][bt][0];
            Ct[(bl + 1) * CST + jl]     = acc[jt][bt][1];
            Ct[bl * CST + jl + 8]       = acc[jt][bt][2];
            Ct[(bl + 1) * CST + jl + 8] = acc[jt][bt][3];
        }
    __syncthreads();
#pragma unroll
    for (int p = 0; p < 8; p++) {
        int brow = (tid >> 5) + p * 8;
        int col  = lane * 4;
        float4 c = *(const float4*)&Ct[brow * CST + col];
        int j = j0 + col;
        if (j + 3 < J) {
            float4 o;
            o.x = c.x + bias[j];     o.y = c.y + bias[j + 1];
            o.z = c.z + bias[j + 2]; o.w = c.w + bias[j + 3];
            *(float4*)&out[(size_t)brow * ldo + j] = o;
        } else {
            float cv[4] = {c.x, c.y, c.z, c.w};
#pragma unroll
            for (int q = 0; q < 4; q++)
                if (j + q < J) out[(size_t)brow * ldo + j + q] = cv[q] + bias[j + q];
        }
    }
}

// ---------------- K1: GRU gate GEMMs ----------------------------------------
__global__ __launch_bounds__(256, 2) void k_gates_gemm(
    const float* __restrict__ w_ih, const float* __restrict__ w_hh,
    const float* __restrict__ b_ih, const float* __restrict__ b_hh)
{
    __shared__ __align__(16) unsigned char smem[SMEM_BYTES];
    constexpr int NB = H3 / JT;
    bool second = blockIdx.x >= NB;
    int j0 = (second ? blockIdx.x - NB : blockIdx.x) * JT;
    const __nv_bfloat16* Ahi = second ? g_h_hi : g_x_hi;
    const __nv_bfloat16* Alo = second ? g_h_lo : g_x_lo;
    const float* W    = second ? w_hh : w_ih;
    const float* bias = second ? b_hh : b_ih;
    float* out        = second ? g_gh : g_gi;
    mma_gemm_body(smem, Ahi, Alo, W, bias, out, H, H3, H3, j0);
}

// ---------------- K2: GRU gates -> h_new, norms, fp16 cat --------------------
__global__ void k_gru(const float* __restrict__ hid, float* __restrict__ hout) {
    int b = blockIdx.x;
    int j = threadIdx.x;   // blockDim = 1024
    float ir = g_gi[b * H3 + j],          hr = g_gh[b * H3 + j];
    float iz = g_gi[b * H3 + H + j],      hz = g_gh[b * H3 + H + j];
    float in_ = g_gi[b * H3 + 2 * H + j], hn = g_gh[b * H3 + 2 * H + j];
    float r = 1.0f / (1.0f + expf(-(ir + hr)));
    float z = 1.0f / (1.0f + expf(-(iz + hz)));
    float n = tanhf(in_ + r * hn);
    float hv = hid[b * H + j];
    float hnew = (1.0f - z) * n + z * hv;
    hout[b * H + j] = hnew;
    g_cat_f16[b * K2 + j] = __float2half_rn(hnew);

    __shared__ float sm[32];
    float w = warp_sum(hnew * hnew);
    if ((j & 31) == 0) sm[j >> 5] = w;
    __syncthreads();
    if (j == 0) {
        float t = 0.0f;
#pragma unroll
        for (int i = 0; i < 32; i++) t += sm[i];
        g_norm[b] = fmaxf(sqrtf(t), 1e-7f);
    }
}

// ---------------- K3: cosine similarity sim[l,b] (float4) --------------------
__global__ void k_sim(const float* __restrict__ enc, const float* __restrict__ hnew) {
    int l = blockIdx.x, b = blockIdx.y;
    const float4* e4 = (const float4*)(enc + ((size_t)l * B + b) * H);
    const float4* h4 = (const float4*)(hnew + (size_t)b * H);
    float dot = 0.0f, sq = 0.0f;
#pragma unroll
    for (int i = 0; i < 2; i++) {
        float4 ev = e4[threadIdx.x + i * 128];
        float4 hv = h4[threadIdx.x + i * 128];
        dot += ev.x * hv.x + ev.y * hv.y + ev.z * hv.z + ev.w * hv.w;
        sq  += ev.x * ev.x + ev.y * ev.y + ev.z * ev.z + ev.w * ev.w;
    }
    __shared__ float sd[4], sq_s[4];
    float d = warp_sum(dot), s = warp_sum(sq);
    int wid = threadIdx.x >> 5;
    if ((threadIdx.x & 31) == 0) { sd[wid] = d; sq_s[wid] = s; }
    __syncthreads();
    if (threadIdx.x == 0) {
        float dt = sd[0] + sd[1] + sd[2] + sd[3];
        float st = sq_s[0] + sq_s[1] + sq_s[2] + sq_s[3];
        float en = fmaxf(sqrtf(st), 1e-7f);
        g_sim[b * L + l] = dt / (g_norm[b] * en);
    }
}

// ---------------- K4: softmax over l ----------------------------------------
__global__ void k_softmax(float* __restrict__ aout) {
    int b = blockIdx.x, l = threadIdx.x;
    float v = g_sim[b * L + l];
    __shared__ float sm[8];
    __shared__ float bcast;
    float m = warp_max(v);
    if ((l & 31) == 0) sm[l >> 5] = m;
    __syncthreads();
    if (l == 0) {
        float t = sm[0];
#pragma unroll
        for (int i = 1; i < 8; i++) t = fmaxf(t, sm[i]);
        bcast = t;
    }
    __syncthreads();
    float e = expf(v - bcast);
    float s = warp_sum(e);
    if ((l & 31) == 0) sm[l >> 5] = s;
    __syncthreads();
    if (l == 0) {
        float t = 0.0f;
#pragma unroll
        for (int i = 0; i < 8; i++) t += sm[i];
        bcast = t;
    }
    __syncthreads();
    float a = e / bcast;
    g_attn[b * L + l] = a;
    aout[b * L + l] = a;
}

// ---------------- K5: context vector -> fp16 cat -----------------------------
__global__ void k_ctx(const float* __restrict__ enc) {
    int b = blockIdx.y;
    int h = blockIdx.x * 256 + threadIdx.x;
    __shared__ float sa[L];
    if (threadIdx.x < L) sa[threadIdx.x] = g_attn[b * L + threadIdx.x];
    __syncthreads();
    float s0 = 0.f, s1 = 0.f, s2 = 0.f, s3 = 0.f;
#pragma unroll 4
    for (int l = 0; l < L; l += 4) {
        s0 += sa[l]     * enc[((size_t)l * B + b) * H + h];
        s1 += sa[l + 1] * enc[((size_t)(l + 1) * B + b) * H + h];
        s2 += sa[l + 2] * enc[((size_t)(l + 2) * B + b) * H + h];
        s3 += sa[l + 3] * enc[((size_t)(l + 3) * B + b) * H + h];
    }
    float s = (s0 + s1) + (s2 + s3);
    g_cat_f16[(size_t)b * K2 + H + h] = __float2half_rn(s);
}

// ---------------- K6: logits GEMM (fp16 single-pass, KT=64) ------------------
__global__ __launch_bounds__(256, 2) void k_logits_f16(
    const float* __restrict__ W, const float* __restrict__ bias,
    float* __restrict__ out)
{
    extern __shared__ __align__(16) unsigned char dsm[];
    const uint32_t smem_u32 = (uint32_t)__cvta_generic_to_shared(dsm);
    const int tid  = threadIdx.x;
    const int lane = tid & 31;
    const int wid  = tid >> 5;
    const int grp  = lane >> 2;
    const int qd   = lane & 3;
    const int jw   = (wid >> 1) * 32;
    const int bw   = (wid & 1) * 32;
    const int j0   = blockIdx.x * LTJ;
    const int swz  = (grp & 3) * 8;

    const int wrow0 = tid >> 4;          // + i*16
    const int wcol  = (tid & 15) * 4;
    const int arow = tid >> 2;
    const int acol = (tid & 3) * 16;

    float acc[2][4][4];
#pragma unroll
    for (int jt = 0; jt < 2; jt++)
#pragma unroll
        for (int bt = 0; bt < 4; bt++)
#pragma unroll
            for (int q = 0; q < 4; q++) acc[jt][bt][q] = 0.0f;

    const __half* Asrc = g_cat_f16 + (size_t)arow * K2 + acol;

    // ---- prologue: A(0) -> buf0; A(1) -> regs; W(0),W(1) cp.async -----------
    {
        __half* sA = (__half*)(dsm + LA_OFF);
        *(uint4*)&sA[arow * L_AST + acol]     = *(const uint4*)Asrc;
        *(uint4*)&sA[arow * L_AST + acol + 8] = *(const uint4*)(Asrc + 8);
    }
    uint4 ra0 = *(const uint4*)(Asrc + LTK);
    uint4 ra1 = *(const uint4*)(Asrc + LTK + 8);

#pragma unroll
    for (int s = 0; s < 2; s++) {
        uint32_t wb = smem_u32 + s * LW_BUF;
#pragma unroll
        for (int i = 0; i < 8; i++) {
            int r = wrow0 + i * 16;
            int j = j0 + r; if (j > V - 1) j = V - 1;
            int c = wcol ^ ((r & 3) * 8);
            cp16(wb + (uint32_t)(r * LTK + c) * 4, &W[(size_t)j * K2 + s * LTK + wcol]);
        }
        cp_commit();
    }

    for (int s = 0; s < LNS; s++) {
        if (s + 1 < LNS) asm volatile("cp.async.wait_group 1;" ::: "memory");
        else             asm volatile("cp.async.wait_group 0;" ::: "memory");
        __syncthreads();

        uint4 na0, na1;
        if (s + 2 < LNS) {
            na0 = *(const uint4*)(Asrc + (s + 2) * LTK);
            na1 = *(const uint4*)(Asrc + (s + 2) * LTK + 8);
        }

        const float* sWb = reinterpret_cast<const float*>(dsm + (s & 1) * LW_BUF);
        const __half* sA = (const __half*)(dsm + LA_OFF + (s & 1) * LA_BUF);

#pragma unroll
        for (int ks = 0; ks < LTK; ks += 16) {
            const int kc = ks + qd * 2;
            const int c0 = kc ^ swz;
            const int c1 = (kc + 8) ^ swz;
            uint32_t wh[2][4];
#pragma unroll
            for (int jt = 0; jt < 2; jt++) {
                int r0 = (jw + jt * 16 + grp) * LTK;
                int r1 = r0 + 8 * LTK;
                wh[jt][0] = f2h2(*(const float2*)&sWb[r0 + c0]);
                wh[jt][1] = f2h2(*(const float2*)&sWb[r1 + c0]);
                wh[jt][2] = f2h2(*(const float2*)&sWb[r0 + c1]);
                wh[jt][3] = f2h2(*(const float2*)&sWb[r1 + c1]);
            }
            uint32_t ah[4][2];
#pragma unroll
            for (int bt = 0; bt < 4; bt++) {
                int br = bw + bt * 8 + grp;
                ah[bt][0] = lds2h(&sA[br * L_AST + kc]);
                ah[bt][1] = lds2h(&sA[br * L_AST + kc + 8]);
            }
#pragma unroll
            for (int jt = 0; jt < 2; jt++)
#pragma unroll
                for (int bt = 0; bt < 4; bt++)
                    mma_f16(acc[jt][bt], wh[jt], ah[bt]);
        }
        __syncthreads();

        if (s + 1 < LNS) {   // store A(s+1) into the other A buffer
            __half* sAn = (__half*)(dsm + LA_OFF + ((s + 1) & 1) * LA_BUF);
            *(uint4*)&sAn[arow * L_AST + acol]     = ra0;
            *(uint4*)&sAn[arow * L_AST + acol + 8] = ra1;
            ra0 = na0; ra1 = na1;
        }
        if (s + 2 < LNS) {   // issue W(s+2)
            uint32_t wb = smem_u32 + ((s + 2) & 1) * LW_BUF;
#pragma unroll
            for (int i = 0; i < 8; i++) {
                int r = wrow0 + i * 16;
                int j = j0 + r; if (j > V - 1) j = V - 1;
                int c = wcol ^ ((r & 3) * 8);
                cp16(wb + (uint32_t)(r * LTK + c) * 4,
                     &W[(size_t)j * K2 + (s + 2) * LTK + wcol]);
            }
            cp_commit();
        }
    }

    // ---- epilogue: stage C in smem (transpose), coalesced stores ------------
    float* Ct = reinterpret_cast<float*>(dsm);
#pragma unroll
    for (int jt = 0; jt < 2; jt++)
#pragma unroll
        for (int bt = 0; bt < 4; bt++) {
            int jl = jw + jt * 16 + grp;
            int bl = bw + bt * 8 + qd * 2;
            Ct[bl * CST + jl]           = acc[jt][bt][0];
            Ct[(bl + 1) * CST + jl]     = acc[jt][bt][1];
            Ct[bl * CST + jl + 8]       = acc[jt][bt][2];
            Ct[(bl + 1) * CST + jl + 8] = acc[jt][bt][3];
        }
    __syncthreads();
#pragma unroll
    for (int p = 0; p < 8; p++) {
        int brow = (tid >> 5) + p * 8;
        int col  = lane * 4;
        float4 c = *(const float4*)&Ct[brow * CST + col];
        int j = j0 + col;
        if (j + 3 < V) {
            float4 o;
            o.x = c.x + bias[j];     o.y = c.y + bias[j + 1];
            o.z = c.z + bias[j + 2]; o.w = c.w + bias[j + 3];
            *(float4*)&out[(size_t)brow * V + j] = o;
        } else {
            float cv[4] = {c.x, c.y, c.z, c.w};
#pragma unroll
            for (int q = 0; q < 4; q++)
                if (j + q < V) out[(size_t)brow * V + j + q] = cv[q] + bias[j + q];
        }
    }
}

// ---------------- K7: log_softmax over V, in place (float4) ------------------
__global__ void k_lse(float* __restrict__ logp) {
    int b = blockIdx.x;
    float* row = logp + (size_t)b * V;
    float4* row4 = reinterpret_cast<float4*>(row);
    constexpr int V4 = V / 4;
    __shared__ float sm[32];
    __shared__ float bcast;
    int tid = threadIdx.x, wid = tid >> 5, lane = tid & 31;

    float m = -3.4e38f;
    for (int v = tid; v < V4; v += 1024) {
        float4 c = row4[v];
        m = fmaxf(m, fmaxf(fmaxf(c.x, c.y), fmaxf(c.z, c.w)));
    }
    m = warp_max(m);
    if (lane == 0) sm[wid] = m;
    __syncthreads();
    if (tid == 0) {
        float t = sm[0];
#pragma unroll
        for (int i = 1; i < 32; i++) t = fmaxf(t, sm[i]);
        bcast = t;
    }
    __syncthreads();
    float bm = bcast;

    float s = 0.0f;
    for (int v = tid; v < V4; v += 1024) {
        float4 c = row4[v];
        s += expf(c.x - bm) + expf(c.y - bm) + expf(c.z - bm) + expf(c.w - bm);
    }
    s = warp_sum(s);
    if (lane == 0) sm[wid] = s;
    __syncthreads();
    if (tid == 0) {
        float t = 0.0f;
#pragma unroll
        for (int i = 0; i < 32; i++) t += sm[i];
        bcast = bm + logf(t);
    }
    __syncthreads();
    float ls = bcast;
    for (int v = tid; v < V4; v += 1024) {
        float4 c = row4[v];
        c.x -= ls; c.y -= ls; c.z -= ls; c.w -= ls;
        row4[v] = c;
    }
}

// ---------------- launch -----------------------------------------------------
extern "C" void kernel_launch(void* const* d_in, const int* in_sizes, int n_in,
                              void* d_out, int out_size) {
    const int*   ids   = (const int*)  d_in[0];
    const float* hid   = (const float*)d_in[1];
    const float* enc   = (const float*)d_in[2];
    const float* emb   = (const float*)d_in[3];
    const float* w_ih  = (const float*)d_in[4];
    const float* w_hh  = (const float*)d_in[5];
    const float* b_ih  = (const float*)d_in[6];
    const float* b_hh  = (const float*)d_in[7];
    const float* w_out = (const float*)d_in[8];
    const float* b_out = (const float*)d_in[9];

    float* out  = (float*)d_out;
    float* logp = out;                       // [B][V]
    float* hout = out + (size_t)B * V;       // [1][B][H]
    float* aout = hout + (size_t)B * H;      // [B][L]

    cudaFuncSetAttribute(k_logits_f16,
                         cudaFuncAttributeMaxDynamicSharedMemorySize, L_SMEM);

    k_embed<<<B, 256>>>(ids, emb);
    k_split_hid<<<(B * H + 255) / 256, 256>>>(hid);
    k_gates_gemm<<<2 * (H3 / JT), 256>>>(w_ih, w_hh, b_ih, b_hh);
    k_gru<<<B, 1024>>>(hid, hout);
    dim3 gs(L, B);
    k_sim<<<gs, 128>>>(enc, hout);
    k_softmax<<<B, L>>>(aout);
    dim3 gc(H / 256, B);
    k_ctx<<<gc, 256>>>(enc);
    k_logits_f16<<<(V + LTJ - 1) / LTJ, 256, L_SMEM>>>(w_out, b_out, logp);
    k_lse<<<B, 1024>>>(logp);
}

// round 12
// speedup vs baseline: 1.7000x; 1.0942x over previous
#include <cuda_runtime.h>
#include <cuda_fp16.h>
#include <math.h>
#include <stdint.h>

namespace {
constexpr int H  = 1024;
constexpr int V  = 50000;
constexpr int B  = 64;
constexpr int L  = 256;
constexpr int H3 = 3 * H;
constexpr int K2 = 2 * H;

// ---- unified fp16 GEMM (mma.sync f16 1-pass, KT=64, dynamic smem) ----
constexpr int LTJ    = 128;                 // j rows per block
constexpr int LTK    = 64;                  // k per stage
constexpr int LW_BUF = LTJ * LTK * 4;       // 32768 bytes per W stage buffer (fp32)
constexpr int L_AST  = 72;                  // A smem row stride (fp16 elements)
constexpr int LA_OFF = 2 * LW_BUF;          // 65536
constexpr int LA_BUF = 64 * L_AST * 2;      // 9216 bytes per A buffer
constexpr int L_SMEM = LA_OFF + 2 * LA_BUF; // 83968
constexpr int CST    = 132;                 // epilogue C tile stride (floats)
}

// ---------------- scratch (device globals) ----------------------------------
__device__ __align__(16) __half g_x_f16[B * H];         // relu(emb) fp16
__device__ __align__(16) __half g_h_f16[B * H];         // hidden fp16
__device__ __align__(16) __half g_cat_f16[B * K2];      // [h_new | ctx] fp16
__device__ __align__(16) float g_gi[B * H3];
__device__ __align__(16) float g_gh[B * H3];
__device__ float g_norm[B];
__device__ float g_sim[B * L];
__device__ float g_attn[B * L];

// ---------------- helpers ----------------------------------------------------
__device__ __forceinline__ float warp_sum(float v) {
#pragma unroll
    for (int o = 16; o > 0; o >>= 1) v += __shfl_xor_sync(0xFFFFFFFFu, v, o);
    return v;
}
__device__ __forceinline__ float warp_max(float v) {
#pragma unroll
    for (int o = 16; o > 0; o >>= 1) v = fmaxf(v, __shfl_xor_sync(0xFFFFFFFFu, v, o));
    return v;
}
__device__ __forceinline__ uint32_t lds2h(const __half* p) {
    return *reinterpret_cast<const uint32_t*>(p);
}
// float2 -> packed fp16x2 (RN)
__device__ __forceinline__ uint32_t f2h2(float2 f) {
    uint32_t h;
    asm("cvt.rn.f16x2.f32 %0, %1, %2;" : "=r"(h) : "f"(f.y), "f"(f.x));
    return h;
}
__device__ __forceinline__ void mma_f16(float* d, const uint32_t* a, const uint32_t* b) {
    asm volatile(
        "mma.sync.aligned.m16n8k16.row.col.f32.f16.f16.f32 "
        "{%0,%1,%2,%3}, {%4,%5,%6,%7}, {%8,%9}, {%0,%1,%2,%3};\n"
        : "+f"(d[0]), "+f"(d[1]), "+f"(d[2]), "+f"(d[3])
        : "r"(a[0]), "r"(a[1]), "r"(a[2]), "r"(a[3]), "r"(b[0]), "r"(b[1]));
}
__device__ __forceinline__ void cp16(uint32_t dst, const void* src) {
    asm volatile("cp.async.cg.shared.global [%0], [%1], 16;\n" :: "r"(dst), "l"(src));
}
__device__ __forceinline__ void cp_commit() {
    asm volatile("cp.async.commit_group;\n" ::: "memory");
}

// ---------------- K1: prep = embed gather+relu AND hid, both -> fp16 ---------
__global__ void k_prep(const int* __restrict__ ids, const float* __restrict__ emb,
                       const float* __restrict__ hid) {
    if (blockIdx.x < B) {
        int b = blockIdx.x;
        const float* src = emb + (size_t)ids[b] * H;
#pragma unroll
        for (int k = 0; k < 4; k++) {
            int h = threadIdx.x + k * 256;
            g_x_f16[b * H + h] = __float2half_rn(fmaxf(src[h], 0.0f));
        }
    } else {
        int base = (blockIdx.x - B) * 4096;
#pragma unroll
        for (int k = 0; k < 16; k++) {
            int i = base + threadIdx.x + k * 256;
            g_h_f16[i] = __float2half_rn(hid[i]);
        }
    }
}

// ---------------- unified pipelined fp16 GEMM body ---------------------------
// out[b][j] = sum_k A[b][k] * W[j][k] + bias[j]
// W fp32 [J][Kfull] streamed via cp.async (double-buffered, XOR-swizzled),
// converted to fp16 at fragment load. A fp16 [64][Kfull], double-buffered.
// Block: 128 j x 64 b, 256 threads.
__device__ __forceinline__ void gemm_f16_body(
    unsigned char* dsm,
    const __half* __restrict__ A, const float* __restrict__ W,
    const float* __restrict__ bias, float* __restrict__ out,
    int K, int J, int ldo, int j0)
{
    const uint32_t smem_u32 = (uint32_t)__cvta_generic_to_shared(dsm);
    const int tid  = threadIdx.x;
    const int lane = tid & 31;
    const int wid  = tid >> 5;
    const int grp  = lane >> 2;
    const int qd   = lane & 3;
    const int jw   = (wid >> 1) * 32;
    const int bw   = (wid & 1) * 32;
    const int swz  = (grp & 3) * 8;
    const int nk   = K / LTK;

    const int wrow0 = tid >> 4;          // + i*16
    const int wcol  = (tid & 15) * 4;
    const int arow  = tid >> 2;
    const int acol  = (tid & 3) * 16;

    float acc[2][4][4];
#pragma unroll
    for (int jt = 0; jt < 2; jt++)
#pragma unroll
        for (int bt = 0; bt < 4; bt++)
#pragma unroll
            for (int q = 0; q < 4; q++) acc[jt][bt][q] = 0.0f;

    const __half* Asrc = A + (size_t)arow * K + acol;

    // ---- prologue: A(0) -> buf0; A(1) -> regs; W(0),W(1) cp.async -----------
    {
        __half* sA = (__half*)(dsm + LA_OFF);
        *(uint4*)&sA[arow * L_AST + acol]     = *(const uint4*)Asrc;
        *(uint4*)&sA[arow * L_AST + acol + 8] = *(const uint4*)(Asrc + 8);
    }
    uint4 ra0 = *(const uint4*)(Asrc + LTK);
    uint4 ra1 = *(const uint4*)(Asrc + LTK + 8);

#pragma unroll
    for (int s = 0; s < 2; s++) {
        uint32_t wb = smem_u32 + s * LW_BUF;
#pragma unroll
        for (int i = 0; i < 8; i++) {
            int r = wrow0 + i * 16;
            int j = j0 + r; if (j > J - 1) j = J - 1;
            int c = wcol ^ ((r & 3) * 8);
            cp16(wb + (uint32_t)(r * LTK + c) * 4, &W[(size_t)j * K + s * LTK + wcol]);
        }
        cp_commit();
    }

    for (int s = 0; s < nk; s++) {
        if (s + 1 < nk) asm volatile("cp.async.wait_group 1;" ::: "memory");
        else            asm volatile("cp.async.wait_group 0;" ::: "memory");
        __syncthreads();

        uint4 na0, na1;
        if (s + 2 < nk) {
            na0 = *(const uint4*)(Asrc + (s + 2) * LTK);
            na1 = *(const uint4*)(Asrc + (s + 2) * LTK + 8);
        }

        const float* sWb = reinterpret_cast<const float*>(dsm + (s & 1) * LW_BUF);
        const __half* sA = (const __half*)(dsm + LA_OFF + (s & 1) * LA_BUF);

#pragma unroll
        for (int ks = 0; ks < LTK; ks += 16) {
            const int kc = ks + qd * 2;
            const int c0 = kc ^ swz;
            const int c1 = (kc + 8) ^ swz;
            uint32_t wh[2][4];
#pragma unroll
            for (int jt = 0; jt < 2; jt++) {
                int r0 = (jw + jt * 16 + grp) * LTK;
                int r1 = r0 + 8 * LTK;
                wh[jt][0] = f2h2(*(const float2*)&sWb[r0 + c0]);
                wh[jt][1] = f2h2(*(const float2*)&sWb[r1 + c0]);
                wh[jt][2] = f2h2(*(const float2*)&sWb[r0 + c1]);
                wh[jt][3] = f2h2(*(const float2*)&sWb[r1 + c1]);
            }
            uint32_t ah[4][2];
#pragma unroll
            for (int bt = 0; bt < 4; bt++) {
                int br = bw + bt * 8 + grp;
                ah[bt][0] = lds2h(&sA[br * L_AST + kc]);
                ah[bt][1] = lds2h(&sA[br * L_AST + kc + 8]);
            }
#pragma unroll
            for (int jt = 0; jt < 2; jt++)
#pragma unroll
                for (int bt = 0; bt < 4; bt++)
                    mma_f16(acc[jt][bt], wh[jt], ah[bt]);
        }
        __syncthreads();

        if (s + 1 < nk) {   // store A(s+1) into the other A buffer
            __half* sAn = (__half*)(dsm + LA_OFF + ((s + 1) & 1) * LA_BUF);
            *(uint4*)&sAn[arow * L_AST + acol]     = ra0;
            *(uint4*)&sAn[arow * L_AST + acol + 8] = ra1;
            ra0 = na0; ra1 = na1;
        }
        if (s + 2 < nk) {   // issue W(s+2)
            uint32_t wb = smem_u32 + ((s + 2) & 1) * LW_BUF;
#pragma unroll
            for (int i = 0; i < 8; i++) {
                int r = wrow0 + i * 16;
                int j = j0 + r; if (j > J - 1) j = J - 1;
                int c = wcol ^ ((r & 3) * 8);
                cp16(wb + (uint32_t)(r * LTK + c) * 4,
                     &W[(size_t)j * K + (s + 2) * LTK + wcol]);
            }
            cp_commit();
        }
    }

    // ---- epilogue: stage C in smem (transpose), coalesced stores ------------
    float* Ct = reinterpret_cast<float*>(dsm);
#pragma unroll
    for (int jt = 0; jt < 2; jt++)
#pragma unroll
        for (int bt = 0; bt < 4; bt++) {
            int jl = jw + jt * 16 + grp;
            int bl = bw + bt * 8 + qd * 2;
            Ct[bl * CST + jl]           = acc[jt][bt][0];
            Ct[(bl + 1) * CST + jl]     = acc[jt][bt][1];
            Ct[bl * CST + jl + 8]       = acc[jt][bt][2];
            Ct[(bl + 1) * CST + jl + 8] = acc[jt][bt][3];
        }
    __syncthreads();
#pragma unroll
    for (int p = 0; p < 8; p++) {
        int brow = (tid >> 5) + p * 8;
        int col  = lane * 4;
        float4 c = *(const float4*)&Ct[brow * CST + col];
        int j = j0 + col;
        if (j + 3 < J) {
            float4 o;
            o.x = c.x + bias[j];     o.y = c.y + bias[j + 1];
            o.z = c.z + bias[j + 2]; o.w = c.w + bias[j + 3];
            *(float4*)&out[(size_t)brow * ldo + j] = o;
        } else {
            float cv[4] = {c.x, c.y, c.z, c.w};
#pragma unroll
            for (int q = 0; q < 4; q++)
                if (j + q < J) out[(size_t)brow * ldo + j + q] = cv[q] + bias[j + q];
        }
    }
}

// ---------------- K2: GRU gate GEMMs (fp16 1-pass) ---------------------------
__global__ __launch_bounds__(256, 2) void k_gates_f16(
    const float* __restrict__ w_ih, const float* __restrict__ w_hh,
    const float* __restrict__ b_ih, const float* __restrict__ b_hh)
{
    extern __shared__ __align__(16) unsigned char dsm[];
    constexpr int NB = H3 / LTJ;   // 24 blocks per GEMM
    bool second = blockIdx.x >= NB;
    int j0 = (second ? blockIdx.x - NB : blockIdx.x) * LTJ;
    const __half* A   = second ? g_h_f16 : g_x_f16;
    const float* W    = second ? w_hh : w_ih;
    const float* bias = second ? b_hh : b_ih;
    float* out        = second ? g_gh : g_gi;
    gemm_f16_body(dsm, A, W, bias, out, H, H3, H3, j0);
}

// ---------------- K6: logits GEMM (fp16 1-pass) ------------------------------
__global__ __launch_bounds__(256, 2) void k_logits_f16(
    const float* __restrict__ w_out, const float* __restrict__ b_out,
    float* __restrict__ logp)
{
    extern __shared__ __align__(16) unsigned char dsm[];
    gemm_f16_body(dsm, g_cat_f16, w_out, b_out, logp, K2, V, V, blockIdx.x * LTJ);
}

// ---------------- K3: GRU gates -> h_new, norms, fp16 cat --------------------
__global__ void k_gru(const float* __restrict__ hid, float* __restrict__ hout) {
    int b = blockIdx.x;
    int j = threadIdx.x;   // blockDim = 1024
    float ir = g_gi[b * H3 + j],          hr = g_gh[b * H3 + j];
    float iz = g_gi[b * H3 + H + j],      hz = g_gh[b * H3 + H + j];
    float in_ = g_gi[b * H3 + 2 * H + j], hn = g_gh[b * H3 + 2 * H + j];
    float r = 1.0f / (1.0f + expf(-(ir + hr)));
    float z = 1.0f / (1.0f + expf(-(iz + hz)));
    float n = tanhf(in_ + r * hn);
    float hv = hid[b * H + j];
    float hnew = (1.0f - z) * n + z * hv;
    hout[b * H + j] = hnew;
    g_cat_f16[b * K2 + j] = __float2half_rn(hnew);

    __shared__ float sm[32];
    float w = warp_sum(hnew * hnew);
    if ((j & 31) == 0) sm[j >> 5] = w;
    __syncthreads();
    if (j == 0) {
        float t = 0.0f;
#pragma unroll
        for (int i = 0; i < 32; i++) t += sm[i];
        g_norm[b] = fmaxf(sqrtf(t), 1e-7f);
    }
}

// ---------------- K4: cosine similarity sim[l,b] (float4) --------------------
__global__ void k_sim(const float* __restrict__ enc, const float* __restrict__ hnew) {
    int l = blockIdx.x, b = blockIdx.y;
    const float4* e4 = (const float4*)(enc + ((size_t)l * B + b) * H);
    const float4* h4 = (const float4*)(hnew + (size_t)b * H);
    float dot = 0.0f, sq = 0.0f;
#pragma unroll
    for (int i = 0; i < 2; i++) {
        float4 ev = e4[threadIdx.x + i * 128];
        float4 hv = h4[threadIdx.x + i * 128];
        dot += ev.x * hv.x + ev.y * hv.y + ev.z * hv.z + ev.w * hv.w;
        sq  += ev.x * ev.x + ev.y * ev.y + ev.z * ev.z + ev.w * ev.w;
    }
    __shared__ float sd[4], sq_s[4];
    float d = warp_sum(dot), s = warp_sum(sq);
    int wid = threadIdx.x >> 5;
    if ((threadIdx.x & 31) == 0) { sd[wid] = d; sq_s[wid] = s; }
    __syncthreads();
    if (threadIdx.x == 0) {
        float dt = sd[0] + sd[1] + sd[2] + sd[3];
        float st = sq_s[0] + sq_s[1] + sq_s[2] + sq_s[3];
        float en = fmaxf(sqrtf(st), 1e-7f);
        g_sim[b * L + l] = dt / (g_norm[b] * en);
    }
}

// ---------------- K5: softmax over l ----------------------------------------
__global__ void k_softmax(float* __restrict__ aout) {
    int b = blockIdx.x, l = threadIdx.x;
    float v = g_sim[b * L + l];
    __shared__ float sm[8];
    __shared__ float bcast;
    float m = warp_max(v);
    if ((l & 31) == 0) sm[l >> 5] = m;
    __syncthreads();
    if (l == 0) {
        float t = sm[0];
#pragma unroll
        for (int i = 1; i < 8; i++) t = fmaxf(t, sm[i]);
        bcast = t;
    }
    __syncthreads();
    float e = expf(v - bcast);
    float s = warp_sum(e);
    if ((l & 31) == 0) sm[l >> 5] = s;
    __syncthreads();
    if (l == 0) {
        float t = 0.0f;
#pragma unroll
        for (int i = 0; i < 8; i++) t += sm[i];
        bcast = t;
    }
    __syncthreads();
    float a = e / bcast;
    g_attn[b * L + l] = a;
    aout[b * L + l] = a;
}

// ---------------- K5b: context vector -> fp16 cat ----------------------------
__global__ void k_ctx(const float* __restrict__ enc) {
    int b = blockIdx.y;
    int h = blockIdx.x * 256 + threadIdx.x;
    __shared__ float sa[L];
    if (threadIdx.x < L) sa[threadIdx.x] = g_attn[b * L + threadIdx.x];
    __syncthreads();
    float s0 = 0.f, s1 = 0.f, s2 = 0.f, s3 = 0.f;
#pragma unroll 4
    for (int l = 0; l < L; l += 4) {
        s0 += sa[l]     * enc[((size_t)l * B + b) * H + h];
        s1 += sa[l + 1] * enc[((size_t)(l + 1) * B + b) * H + h];
        s2 += sa[l + 2] * enc[((size_t)(l + 2) * B + b) * H + h];
        s3 += sa[l + 3] * enc[((size_t)(l + 3) * B + b) * H + h];
    }
    float s = (s0 + s1) + (s2 + s3);
    g_cat_f16[(size_t)b * K2 + H + h] = __float2half_rn(s);
}

// ---------------- K7: log_softmax over V, in place (float4) ------------------
__global__ void k_lse(float* __restrict__ logp) {
    int b = blockIdx.x;
    float* row = logp + (size_t)b * V;
    float4* row4 = reinterpret_cast<float4*>(row);
    constexpr int V4 = V / 4;
    __shared__ float sm[32];
    __shared__ float bcast;
    int tid = threadIdx.x, wid = tid >> 5, lane = tid & 31;

    float m = -3.4e38f;
    for (int v = tid; v < V4; v += 1024) {
        float4 c = row4[v];
        m = fmaxf(m, fmaxf(fmaxf(c.x, c.y), fmaxf(c.z, c.w)));
    }
    m = warp_max(m);
    if (lane == 0) sm[wid] = m;
    __syncthreads();
    if (tid == 0) {
        float t = sm[0];
#pragma unroll
        for (int i = 1; i < 32; i++) t = fmaxf(t, sm[i]);
        bcast = t;
    }
    __syncthreads();
    float bm = bcast;

    float s = 0.0f;
    for (int v = tid; v < V4; v += 1024) {
        float4 c = row4[v];
        s += expf(c.x - bm) + expf(c.y - bm) + expf(c.z - bm) + expf(c.w - bm);
    }
    s = warp_sum(s);
    if (lane == 0) sm[wid] = s;
    __syncthreads();
    if (tid == 0) {
        float t = 0.0f;
#pragma unroll
        for (int i = 0; i < 32; i++) t += sm[i];
        bcast = bm + logf(t);
    }
    __syncthreads();
    float ls = bcast;
    for (int v = tid; v < V4; v += 1024) {
        float4 c = row4[v];
        c.x -= ls; c.y -= ls; c.z -= ls; c.w -= ls;
        row4[v] = c;
    }
}

// ---------------- launch -----------------------------------------------------
extern "C" void kernel_launch(void* const* d_in, const int* in_sizes, int n_in,
                              void* d_out, int out_size) {
    const int*   ids   = (const int*)  d_in[0];
    const float* hid   = (const float*)d_in[1];
    const float* enc   = (const float*)d_in[2];
    const float* emb   = (const float*)d_in[3];
    const float* w_ih  = (const float*)d_in[4];
    const float* w_hh  = (const float*)d_in[5];
    const float* b_ih  = (const float*)d_in[6];
    const float* b_hh  = (const float*)d_in[7];
    const float* w_out = (const float*)d_in[8];
    const float* b_out = (const float*)d_in[9];

    float* out  = (float*)d_out;
    float* logp = out;                       // [B][V]
    float* hout = out + (size_t)B * V;       // [1][B][H]
    float* aout = hout + (size_t)B * H;      // [B][L]

    cudaFuncSetAttribute(k_gates_f16,
                         cudaFuncAttributeMaxDynamicSharedMemorySize, L_SMEM);
    cudaFuncSetAttribute(k_logits_f16,
                         cudaFuncAttributeMaxDynamicSharedMemorySize, L_SMEM);

    k_prep<<<B + 16, 256>>>(ids, emb, hid);
    k_gates_f16<<<2 * (H3 / LTJ), 256, L_SMEM>>>(w_ih, w_hh, b_ih, b_hh);
    k_gru<<<B, 1024>>>(hid, hout);
    dim3 gs(L, B);
    k_sim<<<gs, 128>>>(enc, hout);
    k_softmax<<<B, L>>>(aout);
    dim3 gc(H / 256, B);
    k_ctx<<<gc, 256>>>(enc);
    k_logits_f16<<<(V + LTJ - 1) / LTJ, 256, L_SMEM>>>(w_out, b_out, logp);
    k_lse<<<B, 1024>>>(logp);
}